// round 13
// baseline (speedup 1.0000x reference)
#include <cuda_runtime.h>
#include <cstdint>

// Problem constants
#define BB 512
#define VV 32768
#define CC 16
#define TT 256          // threads per block
#define GG 8            // B-eighths per CTA (intra-CTA split)
#define BG (BB / GG)    // 64 samples per eighth
#define VT 32           // v per CTA (warp lane = v)

// EMA coefficient: 1 - MOMENTUM = 2/(STEPS_PER_EPOCH+1)
#define ALPHA ((float)(2.0 / 1001.0))

// ---------------------------------------------------------------------------
// Fused, class-sorted, scattered-gather kernel.
// Prologue: warp 0 counting-sorts the 512 labels (deterministic ballot sort).
// Main: thread (v = lane, eighth g = warp) walks its 64 sorted samples in
// class order; per class segment the channel index is constant, so the
// accumulator is a compile-time register — no per-iteration selection.
// Loads: W[b,v,c] 4B scattered (tests 32B DRAM sector granularity: only
// 536MB of W touched if true) + sparse[b,v] lane-coalesced.
// Epilogue: smem reduce across the 8 eighths, EMA/fresh/absent, write out.
// Grid: VV/VT = 1024 CTAs x 8 warps -> ~51 warps/SM.
// ---------------------------------------------------------------------------
__global__ void __launch_bounds__(TT, 6)
fused_centroid_kernel(const float* __restrict__ sparse,
                      const float* __restrict__ W,
                      const int* __restrict__ labels,
                      const float* __restrict__ centroids,
                      const int* __restrict__ initialized,
                      float* __restrict__ out)
{
    __shared__ int   s_ord[BB];              // class-sorted sample indices
    __shared__ int   s_cnt[CC];              // global class counts
    __shared__ int   s_off[CC];              // class segment offsets
    __shared__ float s_red[GG * CC * VT];    // per-eighth accumulators (16 KB)

    const int tid = threadIdx.x;

    // --- deterministic ballot counting sort (warp 0) ---
    if (tid < 32) {
        const int lane = tid;
        const unsigned lt = (1u << lane) - 1u;
        int l[BB / 32];
        #pragma unroll
        for (int k = 0; k < BB / 32; ++k)
            l[k] = labels[k * 32 + lane];

        int base = 0;
        #pragma unroll
        for (int c = 0; c < CC; ++c) {
            if (lane == 0) s_off[c] = base;
            int cbase = base;
            #pragma unroll
            for (int k = 0; k < BB / 32; ++k) {
                const unsigned m = __ballot_sync(0xffffffffu, l[k] == c);
                if (l[k] == c)
                    s_ord[cbase + __popc(m & lt)] = k * 32 + lane;
                cbase += __popc(m);
            }
            if (lane == 0) s_cnt[c] = cbase - base;
            base = cbase;
        }
    }
    __syncthreads();

    const int vl = tid & 31;                 // lane -> v
    const int g  = tid >> 5;                 // warp -> eighth
    const int v  = blockIdx.x * VT + vl;
    const int qbeg = g * BG;
    const int qend = qbeg + BG;

    const float* __restrict__ spv = sparse + v;        // + b*VV
    const float* __restrict__ Wv  = W + (size_t)v * CC; // + b*VV*CC + c

    float accs[CC];

    #pragma unroll
    for (int c = 0; c < CC; ++c) {
        const int segs = s_off[c];
        const int sege = segs + s_cnt[c];
        const int js = (segs > qbeg) ? segs : qbeg;
        const int je = (sege < qend) ? sege : qend;

        float acc = 0.0f;
        int j = js;
        // unroll-4 MLP batch: 8 independent LDGs in flight
        for (; j + 4 <= je; j += 4) {
            int   b[4];
            float wv[4], sv[4];
            #pragma unroll
            for (int i = 0; i < 4; ++i) {
                b[i]  = s_ord[j + i];
                wv[i] = __ldcs(Wv  + ((size_t)b[i] << 19) + c);  // b*VV*CC
                sv[i] = __ldcs(spv + ((size_t)b[i] << 15));      // b*VV
            }
            #pragma unroll
            for (int i = 0; i < 4; ++i)
                acc += fabsf(wv[i] * sv[i]);
        }
        for (; j < je; ++j) {
            const int b = s_ord[j];
            const float wv = __ldcs(Wv  + ((size_t)b << 19) + c);
            const float sv = __ldcs(spv + ((size_t)b << 15));
            acc += fabsf(wv * sv);
        }
        accs[c] = acc;
    }

    // --- reduce across eighths ---
    #pragma unroll
    for (int c = 0; c < CC; ++c)
        s_red[(g * CC + c) * VT + vl] = accs[c];
    __syncthreads();

    // 512 (c, v) outputs per CTA; 256 threads -> 2 each.
    #pragma unroll
    for (int p = tid; p < CC * VT; p += TT) {
        const int c  = p >> 5;
        const int pv = p & 31;
        float sum = 0.0f;
        #pragma unroll
        for (int gg = 0; gg < GG; ++gg)
            sum += s_red[(gg * CC + c) * VT + pv];

        const int n = s_cnt[c];
        const int vo = blockIdx.x * VT + pv;
        const float cen = centroids[(size_t)c * VV + vo];
        float o;
        if (n > 0) {
            const float mean = sum / (float)n;
            o = (initialized[c] != 0) ? (cen + ALPHA * (mean - cen)) : mean;
        } else {
            o = cen;
        }
        out[(size_t)c * VV + vo] = o;
    }
}

// ---------------------------------------------------------------------------
// Launch: graph-capturable, allocation-free. ONE kernel.
// Inputs identified BY ELEMENT COUNT (robust to metadata ordering):
//   W_eff       f32[B,V,C] -> 268435456 elems
//   sparse_vec  f32[B,V]   ->  16777216 elems
//   centroids   f32[C,V]   ->    524288 elems
//   labels      i32[B]     ->       512 elems
//   initialized i32[C]     ->        16 elems (bool widened to int32)
// Output: f32[C,V].
// ---------------------------------------------------------------------------
extern "C" void kernel_launch(void* const* d_in, const int* in_sizes, int n_in,
                              void* d_out, int out_size)
{
    const float* sparse    = nullptr;
    const float* W         = nullptr;
    const int*   labels    = nullptr;
    const float* centroids = nullptr;
    const int*   init      = nullptr;
    float*       out       = (float*)d_out;

    for (int i = 0; i < n_in; ++i) {
        switch (in_sizes[i]) {
            case BB * VV:            sparse    = (const float*)d_in[i]; break; // 16777216
            case BB:                 labels    = (const int*)d_in[i];   break; // 512
            case CC * VV:            centroids = (const float*)d_in[i]; break; // 524288
            case CC:                 init      = (const int*)d_in[i];   break; // 16
            default:                 W         = (const float*)d_in[i]; break; // 268435456
        }
    }

    fused_centroid_kernel<<<VV / VT, TT>>>(sparse, W, labels, centroids, init, out);
}

// round 15
// speedup vs baseline: 1.0574x; 1.0574x over previous
#include <cuda_runtime.h>
#include <cstdint>

// Problem constants
#define BB 512
#define VV 32768
#define CC 16
#define TT 256          // threads per block: 8 warps = 4 quads x 2 halves
#define VT 32           // v per CTA (lane = v)

// EMA coefficient: 1 - MOMENTUM = 2/(STEPS_PER_EPOCH+1)
#define ALPHA ((float)(2.0 / 1001.0))

// ---------------------------------------------------------------------------
// Fused kernel: sorted class segments + quad-specialized scalar gather.
// Warp (q = warp&3, h = warp>>2), lane = v. Warp processes sorted samples of
// classes [4q, 4q+4), half h (~16 per class segment). Channel index is
// constant within a segment -> zero per-iteration selection ALU. DRAM fetches
// 64B per W row regardless (confirmed R13), so requesting only the needed 4B
// keeps traffic at the 1.14 GB floor while cutting SM-side work 4x vs R12.
// Grid: VV/VT = 1024 CTAs x 8 warps, ~8 CTAs/SM.
// ---------------------------------------------------------------------------
__global__ void __launch_bounds__(TT)
fused_centroid_kernel(const float* __restrict__ sparse,
                      const float* __restrict__ W,
                      const int* __restrict__ labels,
                      const float* __restrict__ centroids,
                      const int* __restrict__ initialized,
                      float* __restrict__ out)
{
    __shared__ int   s_ord[BB];            // class-sorted sample indices
    __shared__ int   s_cnt[CC];            // global class counts
    __shared__ int   s_off[CC];            // class segment offsets
    __shared__ float s_red[2 * CC * VT];   // [h][c][v] partials (4 KB)

    const int tid = threadIdx.x;

    // --- deterministic ballot counting sort (warp 0) ---
    if (tid < 32) {
        const int lane = tid;
        const unsigned lt = (1u << lane) - 1u;
        int l[BB / 32];
        #pragma unroll
        for (int k = 0; k < BB / 32; ++k)
            l[k] = labels[k * 32 + lane];

        int base = 0;
        #pragma unroll
        for (int c = 0; c < CC; ++c) {
            if (lane == 0) s_off[c] = base;
            int cbase = base;
            #pragma unroll
            for (int k = 0; k < BB / 32; ++k) {
                const unsigned m = __ballot_sync(0xffffffffu, l[k] == c);
                if (l[k] == c)
                    s_ord[cbase + __popc(m & lt)] = k * 32 + lane;
                cbase += __popc(m);
            }
            if (lane == 0) s_cnt[c] = cbase - base;
            base = cbase;
        }
    }
    __syncthreads();

    const int warp = tid >> 5;
    const int lane = tid & 31;
    const int q    = warp & 3;      // class quad: classes 4q..4q+3
    const int h    = warp >> 2;     // sample half within each segment
    const int v    = blockIdx.x * VT + lane;

    const float* __restrict__ sp = sparse + v;            // + (b<<15)
    const float* __restrict__ Wv = W + (size_t)v * CC;    // + (b<<19) + c

    #pragma unroll
    for (int r = 0; r < 4; ++r) {
        const int c  = 4 * q + r;
        const int n  = s_cnt[c];
        const int n0 = (n + 1) >> 1;                      // h=0 share
        const int js = s_off[c] + (h ? n0 : 0);
        const int je = s_off[c] + (h ? n : n0);
        const float* __restrict__ Wc = Wv + c;

        float acc = 0.0f;
        int j = js;
        // batch-4: 8 independent LDGs in flight
        for (; j + 4 <= je; j += 4) {
            const int b0 = s_ord[j],     b1 = s_ord[j + 1];
            const int b2 = s_ord[j + 2], b3 = s_ord[j + 3];
            const float w0 = __ldcs(Wc + ((size_t)b0 << 19));
            const float w1 = __ldcs(Wc + ((size_t)b1 << 19));
            const float w2 = __ldcs(Wc + ((size_t)b2 << 19));
            const float w3 = __ldcs(Wc + ((size_t)b3 << 19));
            const float x0 = __ldcs(sp + ((size_t)b0 << 15));
            const float x1 = __ldcs(sp + ((size_t)b1 << 15));
            const float x2 = __ldcs(sp + ((size_t)b2 << 15));
            const float x3 = __ldcs(sp + ((size_t)b3 << 15));
            acc += fabsf(w0 * x0);
            acc += fabsf(w1 * x1);
            acc += fabsf(w2 * x2);
            acc += fabsf(w3 * x3);
        }
        for (; j < je; ++j) {
            const int b = s_ord[j];
            acc += fabsf(__ldcs(Wc + ((size_t)b << 19)) *
                         __ldcs(sp + ((size_t)b << 15)));
        }

        s_red[(h * CC + c) * VT + lane] = acc;
    }
    __syncthreads();

    // 512 (c, v) outputs per CTA; 256 threads -> 2 each.
    #pragma unroll
    for (int p = tid; p < CC * VT; p += TT) {
        const int c  = p >> 5;
        const int pv = p & 31;
        const float sum = s_red[(0 * CC + c) * VT + pv] +
                          s_red[(1 * CC + c) * VT + pv];

        const int n  = s_cnt[c];
        const int vo = blockIdx.x * VT + pv;
        const float cen = centroids[(size_t)c * VV + vo];
        float o;
        if (n > 0) {
            const float mean = sum / (float)n;
            o = (initialized[c] != 0) ? (cen + ALPHA * (mean - cen)) : mean;
        } else {
            o = cen;
        }
        out[(size_t)c * VV + vo] = o;
    }
}

// ---------------------------------------------------------------------------
// Launch: graph-capturable, allocation-free. ONE kernel.
// Inputs identified BY ELEMENT COUNT (robust to metadata ordering):
//   W_eff       f32[B,V,C] -> 268435456 elems
//   sparse_vec  f32[B,V]   ->  16777216 elems
//   centroids   f32[C,V]   ->    524288 elems
//   labels      i32[B]     ->       512 elems
//   initialized i32[C]     ->        16 elems (bool widened to int32)
// Output: f32[C,V].
// ---------------------------------------------------------------------------
extern "C" void kernel_launch(void* const* d_in, const int* in_sizes, int n_in,
                              void* d_out, int out_size)
{
    const float* sparse    = nullptr;
    const float* W         = nullptr;
    const int*   labels    = nullptr;
    const float* centroids = nullptr;
    const int*   init      = nullptr;
    float*       out       = (float*)d_out;

    for (int i = 0; i < n_in; ++i) {
        switch (in_sizes[i]) {
            case BB * VV:            sparse    = (const float*)d_in[i]; break; // 16777216
            case BB:                 labels    = (const int*)d_in[i];   break; // 512
            case CC * VV:            centroids = (const float*)d_in[i]; break; // 524288
            case CC:                 init      = (const int*)d_in[i];   break; // 16
            default:                 W         = (const float*)d_in[i]; break; // 268435456
        }
    }

    fused_centroid_kernel<<<VV / VT, TT>>>(sparse, W, labels, centroids, init, out);
}